// round 8
// baseline (speedup 1.0000x reference)
#include <cuda_runtime.h>
#include <cuda_bf16.h>
#include <cstdint>

#define DIMC   512
#define HEADS  8
#define HD     64
#define NTOK   64
#define BATCH  2048
#define MROWS  (BATCH * NTOK)     // 131072
#define SCALE_Q 0.125f
#define PAD    68

// ---------------- device scratch ----------------
__device__ float g_y[(size_t)3 * MROWS * DIMC];                    // Qh|Kh|Vh
__device__ float g_x[(size_t)MROWS * DIMC];                        // attn out
__device__ __align__(128) __nv_bfloat16 g_wblob[(size_t)8 * 512 * 512]; // [g*2+part][n][k]

// ---------------------------------------------------------------------------
// Kernel 0: weights -> hi/lo bf16 blobs, [n][k] row-major.
// ---------------------------------------------------------------------------
__global__ void conv_w(const float* __restrict__ Wq, const float* __restrict__ Wk,
                       const float* __restrict__ Wv, const float* __restrict__ Wp) {
    int idx = blockIdx.x * 256 + threadIdx.x;
    int g   = idx >> 18;
    int rem = idx & 262143;
    const float* W = (g == 0) ? Wq : (g == 1) ? Wk : (g == 2) ? Wv : Wp;
    float w = W[rem];
    __nv_bfloat16 hi = __float2bfloat16(w);
    __nv_bfloat16 lo = __float2bfloat16(w - __bfloat162float(hi));
    g_wblob[(size_t)(g * 2 + 0) * 262144 + rem] = hi;
    g_wblob[(size_t)(g * 2 + 1) * 262144 + rem] = lo;
}

// ---------------------------------------------------------------------------
// GEMM: C[131072,512] = A @ W^T + bias. bf16 hi/lo 3-product mma.sync.
// CTA 128m x 128n, 256 threads = 8 warps (4m x 2n), warp tile 32x64.
// K chunks of 32, 2-stage cp.async pipeline, 2 CTAs/SM (80KB smem, 128 regs).
// cp.async for chunk c+1 issued AFTER barrier(c) -> 2-stage schedule race-free.
// ---------------------------------------------------------------------------
#define KC      32
#define SAK     40
#define OFF_AH  0
#define OFF_AL  (128 * SAK)
#define OFF_BH  (2 * 128 * SAK)
#define OFF_BL  (3 * 128 * SAK)
#define STAGE_E (4 * 128 * SAK)                    // 20480 bf16 elems = 40960 B
#define SMEM_G  (2 * STAGE_E * 2)                  // 81920 bytes

__device__ __forceinline__ void mma16816(float* d, const uint32_t* a, const uint32_t* b) {
    asm volatile(
        "mma.sync.aligned.m16n8k16.row.col.f32.bf16.bf16.f32 "
        "{%0,%1,%2,%3}, {%4,%5,%6,%7}, {%8,%9}, {%0,%1,%2,%3};"
        : "+f"(d[0]), "+f"(d[1]), "+f"(d[2]), "+f"(d[3])
        : "r"(a[0]), "r"(a[1]), "r"(a[2]), "r"(a[3]), "r"(b[0]), "r"(b[1]));
}
__device__ __forceinline__ void ldsm_x4(uint32_t* r, uint32_t addr) {
    asm volatile("ldmatrix.sync.aligned.m8n8.x4.shared.b16 {%0,%1,%2,%3}, [%4];"
        : "=r"(r[0]), "=r"(r[1]), "=r"(r[2]), "=r"(r[3]) : "r"(addr));
}
__device__ __forceinline__ void cp16(uint32_t dst, const void* src) {
    asm volatile("cp.async.cg.shared.global [%0], [%1], 16;" :: "r"(dst), "l"(src));
}
__device__ __forceinline__ uint32_t pack_bf(__nv_bfloat16 a, __nv_bfloat16 b) {
    return (uint32_t)__bfloat16_as_ushort(a) | ((uint32_t)__bfloat16_as_ushort(b) << 16);
}

__global__ __launch_bounds__(256, 2)
void gemm_mma(const float* __restrict__ qin, const float* __restrict__ kin,
              const float* __restrict__ vin, const float* __restrict__ bias,
              float* __restrict__ Cext, int g) {
    extern __shared__ __nv_bfloat16 sm[];
    const uint32_t sb = (uint32_t)__cvta_generic_to_shared(sm);

    const float* A = (g == 0) ? qin : (g == 1) ? kin : (g == 2) ? vin : (const float*)g_x;
    float* C = (g < 3) ? (g_y + (size_t)g * MROWS * DIMC) : Cext;
    const __nv_bfloat16* Wh = g_wblob + (size_t)(g * 2 + 0) * 262144;
    const __nv_bfloat16* Wl = g_wblob + (size_t)(g * 2 + 1) * 262144;

    const int tid  = threadIdx.x;
    const int lane = tid & 31;
    const int wid  = tid >> 5;
    const int wm   = (wid >> 1) * 32;     // 4 m-groups of 32
    const int wn   = (wid & 1) * 64;      // 2 n-groups of 64
    const int n0   = blockIdx.x * 128;
    const int m0   = blockIdx.y * 128;

    // A staging: 2 threads per row, 16 floats each
    const int arow  = tid >> 1;
    const int acolf = (tid & 1) * 16;
    // B staging: 256 threads = 2 parts x 128 rows, 32 bf16 per row
    const int bpart = tid >> 7;
    const int brow  = tid & 127;

    // ldmatrix lane offsets
    const int a_lrow = (lane & 15);
    const int a_lcol = (lane >> 4) * 8;
    const int b_lrow = ((lane >> 4) << 3) + (lane & 7);
    const int b_lcol = ((lane >> 3) & 1) * 8;

    float acc[2][8][4];
    #pragma unroll
    for (int i = 0; i < 2; i++)
        #pragma unroll
        for (int j = 0; j < 8; j++)
            #pragma unroll
            for (int r = 0; r < 4; r++) acc[i][j][r] = 0.f;

    float4 rA[4];

    auto stageB = [&](int c, int st) {
        uint32_t dst = sb + (uint32_t)(st * STAGE_E +
                       (bpart ? OFF_BL : OFF_BH) + brow * SAK) * 2;
        const __nv_bfloat16* src = (bpart ? Wl : Wh) + (size_t)(n0 + brow) * DIMC + c * KC;
        #pragma unroll
        for (int u = 0; u < 4; u++) cp16(dst + u * 16, src + u * 8);
    };
    auto ldgA = [&](int c) {
        const float* src = A + (size_t)(m0 + arow) * DIMC + c * KC + acolf;
        #pragma unroll
        for (int u = 0; u < 4; u++) rA[u] = __ldg((const float4*)(src + u * 4));
    };
    auto stsA = [&](int st) {
        __nv_bfloat16* sAh = sm + st * STAGE_E + OFF_AH + arow * SAK + acolf;
        __nv_bfloat16* sAl = sm + st * STAGE_E + OFF_AL + arow * SAK + acolf;
        #pragma unroll
        for (int u = 0; u < 4; u++) {
            float4 f = rA[u];
            __nv_bfloat16 h0 = __float2bfloat16(f.x), h1 = __float2bfloat16(f.y),
                          h2 = __float2bfloat16(f.z), h3 = __float2bfloat16(f.w);
            __nv_bfloat16 l0 = __float2bfloat16(f.x - __bfloat162float(h0));
            __nv_bfloat16 l1 = __float2bfloat16(f.y - __bfloat162float(h1));
            __nv_bfloat16 l2 = __float2bfloat16(f.z - __bfloat162float(h2));
            __nv_bfloat16 l3 = __float2bfloat16(f.w - __bfloat162float(h3));
            *(uint2*)(sAh + u * 4) = make_uint2(pack_bf(h0, h1), pack_bf(h2, h3));
            *(uint2*)(sAl + u * 4) = make_uint2(pack_bf(l0, l1), pack_bf(l2, l3));
        }
    };
    auto compute = [&](int st) {
        const uint32_t abase = sb + (uint32_t)(st * STAGE_E) * 2;
        #pragma unroll
        for (int ks = 0; ks < 2; ks++) {
            const int kc0 = ks * 16;
            uint32_t bf[8][2];
            uint32_t ah[2][4], al[2][4];
            #pragma unroll
            for (int i = 0; i < 2; i++) {
                uint32_t aaddr = abase + (uint32_t)(OFF_AH +
                    (wm + i * 16 + a_lrow) * SAK + kc0 + a_lcol) * 2;
                ldsm_x4(ah[i], aaddr);
                ldsm_x4(al[i], aaddr + (uint32_t)(OFF_AL - OFF_AH) * 2);
            }
            #pragma unroll
            for (int gg = 0; gg < 4; gg++) {
                uint32_t r[4];
                uint32_t addr = abase + (uint32_t)(OFF_BH +
                    (wn + gg * 16 + b_lrow) * SAK + kc0 + b_lcol) * 2;
                ldsm_x4(r, addr);
                bf[2 * gg][0] = r[0]; bf[2 * gg][1] = r[1];
                bf[2 * gg + 1][0] = r[2]; bf[2 * gg + 1][1] = r[3];
            }
            // pass 1: hi*hi, pass 2: lo*hi
            #pragma unroll
            for (int i = 0; i < 2; i++)
                #pragma unroll
                for (int j = 0; j < 8; j++)
                    mma16816(acc[i][j], ah[i], bf[j]);
            #pragma unroll
            for (int i = 0; i < 2; i++)
                #pragma unroll
                for (int j = 0; j < 8; j++)
                    mma16816(acc[i][j], al[i], bf[j]);
            // B-lo fragments, pass 3: hi*lo
            #pragma unroll
            for (int gg = 0; gg < 4; gg++) {
                uint32_t r[4];
                uint32_t addr = abase + (uint32_t)(OFF_BL +
                    (wn + gg * 16 + b_lrow) * SAK + kc0 + b_lcol) * 2;
                ldsm_x4(r, addr);
                bf[2 * gg][0] = r[0]; bf[2 * gg][1] = r[1];
                bf[2 * gg + 1][0] = r[2]; bf[2 * gg + 1][1] = r[3];
            }
            #pragma unroll
            for (int i = 0; i < 2; i++)
                #pragma unroll
                for (int j = 0; j < 8; j++)
                    mma16816(acc[i][j], ah[i], bf[j]);
        }
    };

    // ---- prologue: stage chunk 0 into buffer 0 ----
    stageB(0, 0);
    asm volatile("cp.async.commit_group;" ::: "memory");
    ldgA(0);
    stsA(0);

    // ---- main pipeline: 16 chunks, 2 stages ----
    // Invariant: stageB(c+1) issued after barrier(c), whose last reader
    // compute(c-1) is then complete in every warp. wait_group 0 before the
    // barrier guarantees B(c) bytes have landed for every thread.
    for (int c = 0; c < 16; c++) {
        const int st  = c & 1;
        const int stn = st ^ 1;
        if (c < 15) ldgA(c + 1);
        asm volatile("cp.async.wait_group 0;" ::: "memory");
        __syncthreads();
        if (c < 15) {
            stageB(c + 1, stn);
            asm volatile("cp.async.commit_group;" ::: "memory");
        }
        compute(st);
        if (c < 15) stsA(stn);
    }

    // ---- epilogue ----
    #pragma unroll
    for (int j = 0; j < 8; j++) {
        int col = n0 + wn + j * 8 + (lane & 3) * 2;
        float b0 = __ldg(bias + col), b1 = __ldg(bias + col + 1);
        #pragma unroll
        for (int i = 0; i < 2; i++) {
            int row = m0 + wm + i * 16 + (lane >> 2);
            *(float2*)(C + (size_t)row * DIMC + col) =
                make_float2(acc[i][j][0] + b0, acc[i][j][1] + b1);
            *(float2*)(C + (size_t)(row + 8) * DIMC + col) =
                make_float2(acc[i][j][2] + b0, acc[i][j][3] + b1);
        }
    }
}

// ---------------------------------------------------------------------------
// Attention per (b,h) — fp32 in SMEM, reads Qh/Kh/Vh from g_y, writes g_x.
// ---------------------------------------------------------------------------
__global__ __launch_bounds__(256, 2)
void attn(const int* __restrict__ mask) {
    extern __shared__ float smf[];
    float* sQT = smf;
    float* sKT = smf + 1 * 64 * PAD;
    float* sV  = smf + 2 * 64 * PAD;
    float* sS  = smf + 3 * 64 * PAD;
    int* smask = (int*)(smf + 4 * 64 * PAD);

    const int blk = blockIdx.x;
    const int h   = blk & (HEADS - 1);
    const int b   = blk >> 3;
    const int tid = threadIdx.x;
    const int tx  = tid & 15;
    const int ty  = tid >> 4;

    const float* Yq = g_y;
    const float* Yk = g_y + (size_t)1 * MROWS * DIMC;
    const float* Yv = g_y + (size_t)2 * MROWS * DIMC;

    if (tid < NTOK) smask[tid] = mask[b * NTOK + tid];
    #pragma unroll
    for (int it = 0; it < 16; it++) {
        int e = tid + it * 256;
        int i = e >> 6, d = e & 63;
        size_t off = (size_t)(b * 64 + i) * 512 + h * 64 + d;
        sQT[d * PAD + i] = Yq[off] * SCALE_Q;
        sKT[d * PAD + i] = Yk[off];
        sV[i * PAD + d]  = Yv[off];
    }
    __syncthreads();

    {
        float acc[4][4] = {};
        #pragma unroll 16
        for (int d = 0; d < 64; d++) {
            const float4 k4 = *(const float4*)(sKT + d * PAD + (ty << 2));
            const float4 q4 = *(const float4*)(sQT + d * PAD + (tx << 2));
            float kk[4] = {k4.x, k4.y, k4.z, k4.w};
            float qq[4] = {q4.x, q4.y, q4.z, q4.w};
            #pragma unroll
            for (int jj = 0; jj < 4; jj++)
                #pragma unroll
                for (int ii = 0; ii < 4; ii++)
                    acc[jj][ii] = fmaf(kk[jj], qq[ii], acc[jj][ii]);
        }
        #pragma unroll
        for (int jj = 0; jj < 4; jj++) {
            int j = (ty << 2) + jj;
            bool keep = (smask[j] != 0);
            #pragma unroll
            for (int ii = 0; ii < 4; ii++)
                sS[j * PAD + (tx << 2) + ii] = keep ? acc[jj][ii] : -10000.0f;
        }
    }
    __syncthreads();

    {
        int row = tid >> 2;
        int p   = tid & 3;
        float vreg[16];
        float m = -1e30f;
        #pragma unroll
        for (int s = 0; s < 16; s++) {
            vreg[s] = sS[(p * 16 + s) * PAD + row];
            m = fmaxf(m, vreg[s]);
        }
        m = fmaxf(m, __shfl_xor_sync(0xffffffffu, m, 1));
        m = fmaxf(m, __shfl_xor_sync(0xffffffffu, m, 2));
        float sum = 0.f;
        #pragma unroll
        for (int s = 0; s < 16; s++) { vreg[s] = __expf(vreg[s] - m); sum += vreg[s]; }
        sum += __shfl_xor_sync(0xffffffffu, sum, 1);
        sum += __shfl_xor_sync(0xffffffffu, sum, 2);
        float inv = 1.0f / sum;
        #pragma unroll
        for (int s = 0; s < 16; s++) sS[(p * 16 + s) * PAD + row] = vreg[s] * inv;
    }
    __syncthreads();

    {
        float acc[4][4] = {};
        #pragma unroll 16
        for (int j = 0; j < 64; j++) {
            const float4 p4 = *(const float4*)(sS + j * PAD + (ty << 2));
            const float4 v4 = *(const float4*)(sV + j * PAD + (tx << 2));
            float pp[4] = {p4.x, p4.y, p4.z, p4.w};
            float vv[4] = {v4.x, v4.y, v4.z, v4.w};
            #pragma unroll
            for (int ii = 0; ii < 4; ii++)
                #pragma unroll
                for (int dd = 0; dd < 4; dd++)
                    acc[ii][dd] = fmaf(pp[ii], vv[dd], acc[ii][dd]);
        }
        #pragma unroll
        for (int ii = 0; ii < 4; ii++) {
            float4 o = make_float4(acc[ii][0], acc[ii][1], acc[ii][2], acc[ii][3]);
            size_t off = ((size_t)b * NTOK + (ty << 2) + ii) * DIMC + h * HD + (tx << 2);
            *(float4*)(g_x + off) = o;
        }
    }
}

// ---------------------------------------------------------------------------
extern "C" void kernel_launch(void* const* d_in, const int* in_sizes, int n_in,
                              void* d_out, int out_size) {
    const float* q    = (const float*)d_in[0];
    const float* k    = (const float*)d_in[1];
    const float* v    = (const float*)d_in[2];
    const int*   mask = (const int*)  d_in[3];
    const float* Wq   = (const float*)d_in[4];
    const float* bq   = (const float*)d_in[5];
    const float* Wk   = (const float*)d_in[6];
    const float* bk   = (const float*)d_in[7];
    const float* Wv   = (const float*)d_in[8];
    const float* bv   = (const float*)d_in[9];
    const float* Wp   = (const float*)d_in[10];
    const float* bp   = (const float*)d_in[11];
    float* out = (float*)d_out;

    const int smemA = 4 * 64 * PAD * (int)sizeof(float) + NTOK * (int)sizeof(int);
    cudaFuncSetAttribute(gemm_mma, cudaFuncAttributeMaxDynamicSharedMemorySize, SMEM_G);
    cudaFuncSetAttribute(attn, cudaFuncAttributeMaxDynamicSharedMemorySize, smemA);

    conv_w<<<4096, 256>>>(Wq, Wk, Wv, Wp);

    dim3 gg(DIMC / 128, MROWS / 128);
    gemm_mma<<<gg, 256, SMEM_G>>>(q, k, v, bq, nullptr, 0);
    gemm_mma<<<gg, 256, SMEM_G>>>(q, k, v, bk, nullptr, 1);
    gemm_mma<<<gg, 256, SMEM_G>>>(q, k, v, bv, nullptr, 2);

    attn<<<BATCH * HEADS, 256, smemA>>>(mask);

    gemm_mma<<<gg, 256, SMEM_G>>>(q, k, v, bp, out, 3);
}

// round 9
// speedup vs baseline: 1.5977x; 1.5977x over previous
#include <cuda_runtime.h>
#include <cuda_fp16.h>
#include <cstdint>

#define DIMC   512
#define HEADS  8
#define HD     64
#define NTOK   64
#define BATCH  2048
#define MROWS  (BATCH * NTOK)     // 131072
#define SCALE_Q 0.125f
#define PAD    68

// ---------------- device scratch ----------------
__device__ float g_y[(size_t)3 * MROWS * DIMC];                    // Qh|Kh|Vh
__device__ float g_x[(size_t)MROWS * DIMC];                        // attn out
__device__ __align__(128) __half g_wblob[(size_t)4 * 512 * 512];   // W hi (fp16) per gemm

// ---------------------------------------------------------------------------
// Kernel 0: weights -> fp16 hi blobs ([n][k] row-major). Only B-hi is needed:
// products computed are A_hi*B_hi + A_lo*B_hi (A carries ~22 mantissa bits).
// ---------------------------------------------------------------------------
__global__ void conv_w(const float* __restrict__ Wq, const float* __restrict__ Wk,
                       const float* __restrict__ Wv, const float* __restrict__ Wp) {
    int idx = blockIdx.x * 256 + threadIdx.x;
    int g   = idx >> 18;
    int rem = idx & 262143;
    const float* W = (g == 0) ? Wq : (g == 1) ? Wk : (g == 2) ? Wv : Wp;
    g_wblob[(size_t)g * 262144 + rem] = __float2half_rn(W[rem]);
}

// ---------------------------------------------------------------------------
// GEMM: C[131072,512] = A @ W^T + bias. fp16 hi/lo 2-product mma.sync.
// CTA 128m x 256n, 512 threads = 16 warps (4m x 4n), warp tile 32x64.
// K chunks of 32, 3-stage cp.async pipeline, ldmatrix fragments.
// ---------------------------------------------------------------------------
#define KC      32
#define SAK     40
#define OFF_AH  0
#define OFF_AL  (128 * SAK)
#define OFF_BH  (2 * 128 * SAK)
#define STAGE_E (2 * 128 * SAK + 256 * SAK)       // 20480 fp16 elems = 40960 B
#define SMEM_G  (3 * STAGE_E * 2)                  // 122880 bytes

__device__ __forceinline__ void mma16816(float* d, const uint32_t* a, const uint32_t* b) {
    asm volatile(
        "mma.sync.aligned.m16n8k16.row.col.f32.f16.f16.f32 "
        "{%0,%1,%2,%3}, {%4,%5,%6,%7}, {%8,%9}, {%0,%1,%2,%3};"
        : "+f"(d[0]), "+f"(d[1]), "+f"(d[2]), "+f"(d[3])
        : "r"(a[0]), "r"(a[1]), "r"(a[2]), "r"(a[3]), "r"(b[0]), "r"(b[1]));
}
__device__ __forceinline__ void ldsm_x4(uint32_t* r, uint32_t addr) {
    asm volatile("ldmatrix.sync.aligned.m8n8.x4.shared.b16 {%0,%1,%2,%3}, [%4];"
        : "=r"(r[0]), "=r"(r[1]), "=r"(r[2]), "=r"(r[3]) : "r"(addr));
}
__device__ __forceinline__ void cp16(uint32_t dst, const void* src) {
    asm volatile("cp.async.cg.shared.global [%0], [%1], 16;" :: "r"(dst), "l"(src));
}
__device__ __forceinline__ uint32_t pack_h(__half a, __half b) {
    return (uint32_t)__half_as_ushort(a) | ((uint32_t)__half_as_ushort(b) << 16);
}

__global__ __launch_bounds__(512, 1)
void gemm_mma(const float* __restrict__ qin, const float* __restrict__ kin,
              const float* __restrict__ vin, const float* __restrict__ bias,
              float* __restrict__ Cext, int g) {
    extern __shared__ __half sm[];
    const uint32_t sb = (uint32_t)__cvta_generic_to_shared(sm);

    const float* A = (g == 0) ? qin : (g == 1) ? kin : (g == 2) ? vin : (const float*)g_x;
    float* C = (g < 3) ? (g_y + (size_t)g * MROWS * DIMC) : Cext;
    const __half* Wh = g_wblob + (size_t)g * 262144;

    const int tid  = threadIdx.x;
    const int lane = tid & 31;
    const int wid  = tid >> 5;
    const int wm   = (wid >> 2) * 32;
    const int wn   = (wid & 3) * 64;
    const int n0   = blockIdx.x * 256;
    const int m0   = blockIdx.y * 128;

    // A staging: 4 threads per row, 8 floats each
    const int arow  = tid >> 2;
    const int acolf = (tid & 3) * 8;
    // B staging: 2 threads per row (256 rows), 16 halves each
    const int brow  = tid >> 1;
    const int bcolf = (tid & 1) * 16;

    // ldmatrix lane offsets
    const int a_lrow = (lane & 15);
    const int a_lcol = (lane >> 4) * 8;
    const int b_lrow = ((lane >> 4) << 3) + (lane & 7);
    const int b_lcol = ((lane >> 3) & 1) * 8;

    float acc[2][8][4];
    #pragma unroll
    for (int i = 0; i < 2; i++)
        #pragma unroll
        for (int j = 0; j < 8; j++)
            #pragma unroll
            for (int r = 0; r < 4; r++) acc[i][j][r] = 0.f;

    float4 rA[2];

    auto stageB = [&](int c, int st) {
        uint32_t dst = sb + (uint32_t)(st * STAGE_E + OFF_BH + brow * SAK + bcolf) * 2;
        const __half* src = Wh + (size_t)(n0 + brow) * DIMC + c * KC + bcolf;
        cp16(dst,      src);
        cp16(dst + 16, src + 8);
    };
    auto ldgA = [&](int c) {
        const float* src = A + (size_t)(m0 + arow) * DIMC + c * KC + acolf;
        rA[0] = __ldg((const float4*)src);
        rA[1] = __ldg((const float4*)(src + 4));
    };
    auto stsA = [&](int st) {
        __half* sAh = sm + st * STAGE_E + OFF_AH + arow * SAK + acolf;
        __half* sAl = sm + st * STAGE_E + OFF_AL + arow * SAK + acolf;
        #pragma unroll
        for (int u = 0; u < 2; u++) {
            float4 f = rA[u];
            __half h0 = __float2half_rn(f.x), h1 = __float2half_rn(f.y),
                   h2 = __float2half_rn(f.z), h3 = __float2half_rn(f.w);
            __half l0 = __float2half_rn(f.x - __half2float(h0));
            __half l1 = __float2half_rn(f.y - __half2float(h1));
            __half l2 = __float2half_rn(f.z - __half2float(h2));
            __half l3 = __float2half_rn(f.w - __half2float(h3));
            *(uint2*)(sAh + u * 4) = make_uint2(pack_h(h0, h1), pack_h(h2, h3));
            *(uint2*)(sAl + u * 4) = make_uint2(pack_h(l0, l1), pack_h(l2, l3));
        }
    };
    auto compute = [&](int st) {
        const uint32_t abase = sb + (uint32_t)(st * STAGE_E) * 2;
        #pragma unroll
        for (int ks = 0; ks < 2; ks++) {
            const int kc0 = ks * 16;
            uint32_t bf[8][2];
            uint32_t ah[2][4], al[2][4];
            #pragma unroll
            for (int i = 0; i < 2; i++) {
                uint32_t aaddr = abase + (uint32_t)(OFF_AH +
                    (wm + i * 16 + a_lrow) * SAK + kc0 + a_lcol) * 2;
                ldsm_x4(ah[i], aaddr);
                ldsm_x4(al[i], aaddr + (uint32_t)(OFF_AL - OFF_AH) * 2);
            }
            #pragma unroll
            for (int gg = 0; gg < 4; gg++) {
                uint32_t r[4];
                uint32_t addr = abase + (uint32_t)(OFF_BH +
                    (wn + gg * 16 + b_lrow) * SAK + kc0 + b_lcol) * 2;
                ldsm_x4(r, addr);
                bf[2 * gg][0] = r[0]; bf[2 * gg][1] = r[1];
                bf[2 * gg + 1][0] = r[2]; bf[2 * gg + 1][1] = r[3];
            }
            // pass 1: hi*hi
            #pragma unroll
            for (int i = 0; i < 2; i++)
                #pragma unroll
                for (int j = 0; j < 8; j++)
                    mma16816(acc[i][j], ah[i], bf[j]);
            // pass 2: lo*hi
            #pragma unroll
            for (int i = 0; i < 2; i++)
                #pragma unroll
                for (int j = 0; j < 8; j++)
                    mma16816(acc[i][j], al[i], bf[j]);
        }
    };

    // ---- prologue ----
    stageB(0, 0);
    asm volatile("cp.async.commit_group;" ::: "memory");
    ldgA(0);
    stsA(0);

    // ---- main pipeline: 16 chunks, 3 stages, 1 barrier per chunk ----
    for (int c = 0; c < 16; c++) {
        const int st  = c % 3;
        const int stn = (c + 1) % 3;
        if (c < 15) {
            ldgA(c + 1);
            stageB(c + 1, stn);
            asm volatile("cp.async.commit_group;" ::: "memory");
            asm volatile("cp.async.wait_group 1;" ::: "memory");
        } else {
            asm volatile("cp.async.wait_group 0;" ::: "memory");
        }
        __syncthreads();
        compute(st);
        if (c < 15) stsA(stn);
    }

    // ---- epilogue ----
    #pragma unroll
    for (int j = 0; j < 8; j++) {
        int col = n0 + wn + j * 8 + (lane & 3) * 2;
        float b0 = __ldg(bias + col), b1 = __ldg(bias + col + 1);
        #pragma unroll
        for (int i = 0; i < 2; i++) {
            int row = m0 + wm + i * 16 + (lane >> 2);
            *(float2*)(C + (size_t)row * DIMC + col) =
                make_float2(acc[i][j][0] + b0, acc[i][j][1] + b1);
            *(float2*)(C + (size_t)(row + 8) * DIMC + col) =
                make_float2(acc[i][j][2] + b0, acc[i][j][3] + b1);
        }
    }
}

// ---------------------------------------------------------------------------
// Attention per (b,h) — fp32 in SMEM, reads Qh/Kh/Vh from g_y, writes g_x.
// ---------------------------------------------------------------------------
__global__ __launch_bounds__(256, 2)
void attn(const int* __restrict__ mask) {
    extern __shared__ float smf[];
    float* sQT = smf;
    float* sKT = smf + 1 * 64 * PAD;
    float* sV  = smf + 2 * 64 * PAD;
    float* sS  = smf + 3 * 64 * PAD;
    int* smask = (int*)(smf + 4 * 64 * PAD);

    const int blk = blockIdx.x;
    const int h   = blk & (HEADS - 1);
    const int b   = blk >> 3;
    const int tid = threadIdx.x;
    const int tx  = tid & 15;
    const int ty  = tid >> 4;

    const float* Yq = g_y;
    const float* Yk = g_y + (size_t)1 * MROWS * DIMC;
    const float* Yv = g_y + (size_t)2 * MROWS * DIMC;

    if (tid < NTOK) smask[tid] = mask[b * NTOK + tid];
    #pragma unroll
    for (int it = 0; it < 16; it++) {
        int e = tid + it * 256;
        int i = e >> 6, d = e & 63;
        size_t off = (size_t)(b * 64 + i) * 512 + h * 64 + d;
        sQT[d * PAD + i] = Yq[off] * SCALE_Q;
        sKT[d * PAD + i] = Yk[off];
        sV[i * PAD + d]  = Yv[off];
    }
    __syncthreads();

    {
        float acc[4][4] = {};
        #pragma unroll 16
        for (int d = 0; d < 64; d++) {
            const float4 k4 = *(const float4*)(sKT + d * PAD + (ty << 2));
            const float4 q4 = *(const float4*)(sQT + d * PAD + (tx << 2));
            float kk[4] = {k4.x, k4.y, k4.z, k4.w};
            float qq[4] = {q4.x, q4.y, q4.z, q4.w};
            #pragma unroll
            for (int jj = 0; jj < 4; jj++)
                #pragma unroll
                for (int ii = 0; ii < 4; ii++)
                    acc[jj][ii] = fmaf(kk[jj], qq[ii], acc[jj][ii]);
        }
        #pragma unroll
        for (int jj = 0; jj < 4; jj++) {
            int j = (ty << 2) + jj;
            bool keep = (smask[j] != 0);
            #pragma unroll
            for (int ii = 0; ii < 4; ii++)
                sS[j * PAD + (tx << 2) + ii] = keep ? acc[jj][ii] : -10000.0f;
        }
    }
    __syncthreads();

    {
        int row = tid >> 2;
        int p   = tid & 3;
        float vreg[16];
        float m = -1e30f;
        #pragma unroll
        for (int s = 0; s < 16; s++) {
            vreg[s] = sS[(p * 16 + s) * PAD + row];
            m = fmaxf(m, vreg[s]);
        }
        m = fmaxf(m, __shfl_xor_sync(0xffffffffu, m, 1));
        m = fmaxf(m, __shfl_xor_sync(0xffffffffu, m, 2));
        float sum = 0.f;
        #pragma unroll
        for (int s = 0; s < 16; s++) { vreg[s] = __expf(vreg[s] - m); sum += vreg[s]; }
        sum += __shfl_xor_sync(0xffffffffu, sum, 1);
        sum += __shfl_xor_sync(0xffffffffu, sum, 2);
        float inv = 1.0f / sum;
        #pragma unroll
        for (int s = 0; s < 16; s++) sS[(p * 16 + s) * PAD + row] = vreg[s] * inv;
    }
    __syncthreads();

    {
        float acc[4][4] = {};
        #pragma unroll 16
        for (int j = 0; j < 64; j++) {
            const float4 p4 = *(const float4*)(sS + j * PAD + (ty << 2));
            const float4 v4 = *(const float4*)(sV + j * PAD + (tx << 2));
            float pp[4] = {p4.x, p4.y, p4.z, p4.w};
            float vv[4] = {v4.x, v4.y, v4.z, v4.w};
            #pragma unroll
            for (int ii = 0; ii < 4; ii++)
                #pragma unroll
                for (int dd = 0; dd < 4; dd++)
                    acc[ii][dd] = fmaf(pp[ii], vv[dd], acc[ii][dd]);
        }
        #pragma unroll
        for (int ii = 0; ii < 4; ii++) {
            float4 o = make_float4(acc[ii][0], acc[ii][1], acc[ii][2], acc[ii][3]);
            size_t off = ((size_t)b * NTOK + (ty << 2) + ii) * DIMC + h * HD + (tx << 2);
            *(float4*)(g_x + off) = o;
        }
    }
}

// ---------------------------------------------------------------------------
extern "C" void kernel_launch(void* const* d_in, const int* in_sizes, int n_in,
                              void* d_out, int out_size) {
    const float* q    = (const float*)d_in[0];
    const float* k    = (const float*)d_in[1];
    const float* v    = (const float*)d_in[2];
    const int*   mask = (const int*)  d_in[3];
    const float* Wq   = (const float*)d_in[4];
    const float* bq   = (const float*)d_in[5];
    const float* Wk   = (const float*)d_in[6];
    const float* bk   = (const float*)d_in[7];
    const float* Wv   = (const float*)d_in[8];
    const float* bv   = (const float*)d_in[9];
    const float* Wp   = (const float*)d_in[10];
    const float* bp   = (const float*)d_in[11];
    float* out = (float*)d_out;

    const int smemA = 4 * 64 * PAD * (int)sizeof(float) + NTOK * (int)sizeof(int);
    cudaFuncSetAttribute(gemm_mma, cudaFuncAttributeMaxDynamicSharedMemorySize, SMEM_G);
    cudaFuncSetAttribute(attn, cudaFuncAttributeMaxDynamicSharedMemorySize, smemA);

    conv_w<<<4096, 256>>>(Wq, Wk, Wv, Wp);

    dim3 gg(DIMC / 256, MROWS / 128);
    gemm_mma<<<gg, 512, SMEM_G>>>(q, k, v, bq, nullptr, 0);
    gemm_mma<<<gg, 512, SMEM_G>>>(q, k, v, bk, nullptr, 1);
    gemm_mma<<<gg, 512, SMEM_G>>>(q, k, v, bv, nullptr, 2);

    attn<<<BATCH * HEADS, 256, smemA>>>(mask);

    gemm_mma<<<gg, 512, SMEM_G>>>(q, k, v, bp, out, 3);
}

// round 10
// speedup vs baseline: 1.6975x; 1.0625x over previous
#include <cuda_runtime.h>
#include <cuda_fp16.h>
#include <cstdint>

#define DIMC   512
#define HEADS  8
#define HD     64
#define NTOK   64
#define BATCH  2048
#define MROWS  (BATCH * NTOK)     // 131072
#define SCALE_Q 0.125f

// ---------------- device scratch ----------------
__device__ float g_y[(size_t)3 * MROWS * DIMC];                    // Qh|Kh|Vh
__device__ float g_x[(size_t)MROWS * DIMC];                        // attn out
__device__ __align__(128) __half g_wblob[(size_t)4 * 512 * 512];   // W hi (fp16)

// ---------------------------------------------------------------------------
// Kernel 0: weights -> fp16 blobs ([n][k] row-major).
// ---------------------------------------------------------------------------
__global__ void conv_w(const float* __restrict__ Wq, const float* __restrict__ Wk,
                       const float* __restrict__ Wv, const float* __restrict__ Wp) {
    int idx = blockIdx.x * 256 + threadIdx.x;
    int g   = idx >> 18;
    int rem = idx & 262143;
    const float* W = (g == 0) ? Wq : (g == 1) ? Wk : (g == 2) ? Wv : Wp;
    g_wblob[(size_t)g * 262144 + rem] = __float2half_rn(W[rem]);
}

// ---------------------------------------------------------------------------
// common MMA helpers
// ---------------------------------------------------------------------------
__device__ __forceinline__ void mma16816(float* d, const uint32_t* a, const uint32_t* b) {
    asm volatile(
        "mma.sync.aligned.m16n8k16.row.col.f32.f16.f16.f32 "
        "{%0,%1,%2,%3}, {%4,%5,%6,%7}, {%8,%9}, {%0,%1,%2,%3};"
        : "+f"(d[0]), "+f"(d[1]), "+f"(d[2]), "+f"(d[3])
        : "r"(a[0]), "r"(a[1]), "r"(a[2]), "r"(a[3]), "r"(b[0]), "r"(b[1]));
}
__device__ __forceinline__ void ldsm_x4(uint32_t* r, uint32_t addr) {
    asm volatile("ldmatrix.sync.aligned.m8n8.x4.shared.b16 {%0,%1,%2,%3}, [%4];"
        : "=r"(r[0]), "=r"(r[1]), "=r"(r[2]), "=r"(r[3]) : "r"(addr));
}
__device__ __forceinline__ void cp16(uint32_t dst, const void* src) {
    asm volatile("cp.async.cg.shared.global [%0], [%1], 16;" :: "r"(dst), "l"(src));
}
__device__ __forceinline__ uint32_t pack_h(__half a, __half b) {
    return (uint32_t)__half_as_ushort(a) | ((uint32_t)__half_as_ushort(b) << 16);
}

// ---------------------------------------------------------------------------
// GEMM: C[131072,512] = A @ W^T + bias. fp16 hi/lo 2-product mma.sync.
// CTA 128m x 256n, 512 threads = 16 warps (4m x 4n), warp tile 32x64.
// (unchanged from R8 — tensor-limited at this schedule)
// ---------------------------------------------------------------------------
#define KC      32
#define SAK     40
#define OFF_AH  0
#define OFF_AL  (128 * SAK)
#define OFF_BH  (2 * 128 * SAK)
#define STAGE_E (2 * 128 * SAK + 256 * SAK)
#define SMEM_G  (3 * STAGE_E * 2)

__global__ __launch_bounds__(512, 1)
void gemm_mma(const float* __restrict__ qin, const float* __restrict__ kin,
              const float* __restrict__ vin, const float* __restrict__ bias,
              float* __restrict__ Cext, int g) {
    extern __shared__ __half sm[];
    const uint32_t sb = (uint32_t)__cvta_generic_to_shared(sm);

    const float* A = (g == 0) ? qin : (g == 1) ? kin : (g == 2) ? vin : (const float*)g_x;
    float* C = (g < 3) ? (g_y + (size_t)g * MROWS * DIMC) : Cext;
    const __half* Wh = g_wblob + (size_t)g * 262144;

    const int tid  = threadIdx.x;
    const int lane = tid & 31;
    const int wid  = tid >> 5;
    const int wm   = (wid >> 2) * 32;
    const int wn   = (wid & 3) * 64;
    const int n0   = blockIdx.x * 256;
    const int m0   = blockIdx.y * 128;

    const int arow  = tid >> 2;
    const int acolf = (tid & 3) * 8;
    const int brow  = tid >> 1;
    const int bcolf = (tid & 1) * 16;

    const int a_lrow = (lane & 15);
    const int a_lcol = (lane >> 4) * 8;
    const int b_lrow = ((lane >> 4) << 3) + (lane & 7);
    const int b_lcol = ((lane >> 3) & 1) * 8;

    float acc[2][8][4];
    #pragma unroll
    for (int i = 0; i < 2; i++)
        #pragma unroll
        for (int j = 0; j < 8; j++)
            #pragma unroll
            for (int r = 0; r < 4; r++) acc[i][j][r] = 0.f;

    float4 rA[2];

    auto stageB = [&](int c, int st) {
        uint32_t dst = sb + (uint32_t)(st * STAGE_E + OFF_BH + brow * SAK + bcolf) * 2;
        const __half* src = Wh + (size_t)(n0 + brow) * DIMC + c * KC + bcolf;
        cp16(dst,      src);
        cp16(dst + 16, src + 8);
    };
    auto ldgA = [&](int c) {
        const float* src = A + (size_t)(m0 + arow) * DIMC + c * KC + acolf;
        rA[0] = __ldg((const float4*)src);
        rA[1] = __ldg((const float4*)(src + 4));
    };
    auto stsA = [&](int st) {
        __half* sAh = sm + st * STAGE_E + OFF_AH + arow * SAK + acolf;
        __half* sAl = sm + st * STAGE_E + OFF_AL + arow * SAK + acolf;
        #pragma unroll
        for (int u = 0; u < 2; u++) {
            float4 f = rA[u];
            __half h0 = __float2half_rn(f.x), h1 = __float2half_rn(f.y),
                   h2 = __float2half_rn(f.z), h3 = __float2half_rn(f.w);
            __half l0 = __float2half_rn(f.x - __half2float(h0));
            __half l1 = __float2half_rn(f.y - __half2float(h1));
            __half l2 = __float2half_rn(f.z - __half2float(h2));
            __half l3 = __float2half_rn(f.w - __half2float(h3));
            *(uint2*)(sAh + u * 4) = make_uint2(pack_h(h0, h1), pack_h(h2, h3));
            *(uint2*)(sAl + u * 4) = make_uint2(pack_h(l0, l1), pack_h(l2, l3));
        }
    };
    auto compute = [&](int st) {
        const uint32_t abase = sb + (uint32_t)(st * STAGE_E) * 2;
        #pragma unroll
        for (int ks = 0; ks < 2; ks++) {
            const int kc0 = ks * 16;
            uint32_t bf[8][2];
            uint32_t ah[2][4], al[2][4];
            #pragma unroll
            for (int i = 0; i < 2; i++) {
                uint32_t aaddr = abase + (uint32_t)(OFF_AH +
                    (wm + i * 16 + a_lrow) * SAK + kc0 + a_lcol) * 2;
                ldsm_x4(ah[i], aaddr);
                ldsm_x4(al[i], aaddr + (uint32_t)(OFF_AL - OFF_AH) * 2);
            }
            #pragma unroll
            for (int gg = 0; gg < 4; gg++) {
                uint32_t r[4];
                uint32_t addr = abase + (uint32_t)(OFF_BH +
                    (wn + gg * 16 + b_lrow) * SAK + kc0 + b_lcol) * 2;
                ldsm_x4(r, addr);
                bf[2 * gg][0] = r[0]; bf[2 * gg][1] = r[1];
                bf[2 * gg + 1][0] = r[2]; bf[2 * gg + 1][1] = r[3];
            }
            #pragma unroll
            for (int i = 0; i < 2; i++)
                #pragma unroll
                for (int j = 0; j < 8; j++)
                    mma16816(acc[i][j], ah[i], bf[j]);
            #pragma unroll
            for (int i = 0; i < 2; i++)
                #pragma unroll
                for (int j = 0; j < 8; j++)
                    mma16816(acc[i][j], al[i], bf[j]);
        }
    };

    stageB(0, 0);
    asm volatile("cp.async.commit_group;" ::: "memory");
    ldgA(0);
    stsA(0);

    for (int c = 0; c < 16; c++) {
        const int st  = c % 3;
        const int stn = (c + 1) % 3;
        if (c < 15) {
            ldgA(c + 1);
            stageB(c + 1, stn);
            asm volatile("cp.async.commit_group;" ::: "memory");
            asm volatile("cp.async.wait_group 1;" ::: "memory");
        } else {
            asm volatile("cp.async.wait_group 0;" ::: "memory");
        }
        __syncthreads();
        compute(st);
        if (c < 15) stsA(stn);
    }

    #pragma unroll
    for (int j = 0; j < 8; j++) {
        int col = n0 + wn + j * 8 + (lane & 3) * 2;
        float b0 = __ldg(bias + col), b1 = __ldg(bias + col + 1);
        #pragma unroll
        for (int i = 0; i < 2; i++) {
            int row = m0 + wm + i * 16 + (lane >> 2);
            *(float2*)(C + (size_t)row * DIMC + col) =
                make_float2(acc[i][j][0] + b0, acc[i][j][1] + b1);
            *(float2*)(C + (size_t)(row + 8) * DIMC + col) =
                make_float2(acc[i][j][2] + b0, acc[i][j][3] + b1);
        }
    }
}

// ---------------------------------------------------------------------------
// Attention per (b,h) — tensor-core fp16 hi/lo. 128 threads = 4 warps, each
// warp owns 16 query rows. S=(Qh+Ql)Kh^T, softmax fp32, O=(Ph+Pl)Vh.
// ---------------------------------------------------------------------------
#define SK2   72                     // fp16 tile stride (ldsm conflict-free)
#define TQH   0                      // 64*72 halves, reused as Ph
#define TQL   4608                   //               reused as Pl
#define TKH   9216
#define TVT   13824                  // V transposed [d][j]
#define OFF_S 36864                  // bytes: fp32 S [64][68]
#define OFF_M 54272                  // bytes: mask ints
#define SMEM_A 54528

__global__ __launch_bounds__(128, 4)
void attn(const int* __restrict__ mask) {
    extern __shared__ __half sha[];
    __half* sQh = sha + TQH;         // -> Ph after softmax
    __half* sQl = sha + TQL;         // -> Pl
    __half* sKh = sha + TKH;
    __half* sVt = sha + TVT;
    float*  sS  = (float*)((char*)sha + OFF_S);
    int*  smask = (int*)((char*)sha + OFF_M);
    const uint32_t sb = (uint32_t)__cvta_generic_to_shared(sha);

    const int blk  = blockIdx.x;
    const int h    = blk & (HEADS - 1);
    const int b    = blk >> 3;
    const int tid  = threadIdx.x;
    const int lane = tid & 31;
    const int wid  = tid >> 5;
    const int wm   = wid * 16;

    const float* Yq = g_y;
    const float* Yk = g_y + (size_t)MROWS * DIMC;
    const float* Yv = g_y + (size_t)2 * MROWS * DIMC;

    if (tid < NTOK) smask[tid] = mask[b * NTOK + tid];

    // ---- load + convert: thread -> row tid>>1, 32 dims at (tid&1)*32 ----
    {
        const int row = tid >> 1;
        const int d0  = (tid & 1) * 32;
        const size_t off = (size_t)(b * 64 + row) * 512 + h * 64 + d0;
        #pragma unroll
        for (int u = 0; u < 8; u++) {
            float4 fq = __ldg((const float4*)(Yq + off + u * 4));
            float4 fk = __ldg((const float4*)(Yk + off + u * 4));
            float4 fv = __ldg((const float4*)(Yv + off + u * 4));
            float qs[4] = {fq.x * SCALE_Q, fq.y * SCALE_Q, fq.z * SCALE_Q, fq.w * SCALE_Q};
            __half qh[4], ql[4];
            #pragma unroll
            for (int e = 0; e < 4; e++) {
                qh[e] = __float2half_rn(qs[e]);
                ql[e] = __float2half_rn(qs[e] - __half2float(qh[e]));
            }
            int d = d0 + u * 4;
            *(uint2*)(sQh + row * SK2 + d) = make_uint2(pack_h(qh[0], qh[1]), pack_h(qh[2], qh[3]));
            *(uint2*)(sQl + row * SK2 + d) = make_uint2(pack_h(ql[0], ql[1]), pack_h(ql[2], ql[3]));
            *(uint2*)(sKh + row * SK2 + d) = make_uint2(
                pack_h(__float2half_rn(fk.x), __float2half_rn(fk.y)),
                pack_h(__float2half_rn(fk.z), __float2half_rn(fk.w)));
            // V transposed: [d][token]
            sVt[(d + 0) * SK2 + row] = __float2half_rn(fv.x);
            sVt[(d + 1) * SK2 + row] = __float2half_rn(fv.y);
            sVt[(d + 2) * SK2 + row] = __float2half_rn(fv.z);
            sVt[(d + 3) * SK2 + row] = __float2half_rn(fv.w);
        }
    }
    __syncthreads();

    const int a_lrow = (lane & 15);
    const int a_lcol = (lane >> 4) * 8;
    const int b_lrow = ((lane >> 4) << 3) + (lane & 7);
    const int b_lcol = ((lane >> 3) & 1) * 8;

    // ---- S = (Qh+Ql) Kh^T : warp rows [wm, wm+16) ----
    {
        float acc[8][4];
        #pragma unroll
        for (int j = 0; j < 8; j++)
            #pragma unroll
            for (int r = 0; r < 4; r++) acc[j][r] = 0.f;
        #pragma unroll
        for (int ks = 0; ks < 4; ks++) {
            const int kc0 = ks * 16;
            uint32_t qh[4], ql[4], bf[8][2];
            uint32_t qaddr = sb + (uint32_t)(TQH + (wm + a_lrow) * SK2 + kc0 + a_lcol) * 2;
            ldsm_x4(qh, qaddr);
            ldsm_x4(ql, qaddr + (uint32_t)(TQL - TQH) * 2);
            #pragma unroll
            for (int gg = 0; gg < 4; gg++) {
                uint32_t r[4];
                ldsm_x4(r, sb + (uint32_t)(TKH + (gg * 16 + b_lrow) * SK2 + kc0 + b_lcol) * 2);
                bf[2 * gg][0] = r[0]; bf[2 * gg][1] = r[1];
                bf[2 * gg + 1][0] = r[2]; bf[2 * gg + 1][1] = r[3];
            }
            #pragma unroll
            for (int j = 0; j < 8; j++) mma16816(acc[j], qh, bf[j]);
            #pragma unroll
            for (int j = 0; j < 8; j++) mma16816(acc[j], ql, bf[j]);
        }
        // write S to smem (fp32, stride 68)
        #pragma unroll
        for (int j = 0; j < 8; j++) {
            int col = j * 8 + (lane & 3) * 2;
            int r0  = wm + (lane >> 2);
            sS[r0 * 68 + col]       = acc[j][0];
            sS[r0 * 68 + col + 1]   = acc[j][1];
            sS[(r0 + 8) * 68 + col]     = acc[j][2];
            sS[(r0 + 8) * 68 + col + 1] = acc[j][3];
        }
    }
    __syncthreads();

    // ---- masked softmax, write P hi/lo over Q tiles ----
    {
        const int row = tid >> 1;
        const int p   = tid & 1;
        float v[32];
        float m = -1e30f;
        #pragma unroll
        for (int s = 0; s < 32; s++) {
            int j = p * 32 + s;
            float sv = sS[row * 68 + j];
            v[s] = (smask[j] != 0) ? sv : -10000.0f;
            m = fmaxf(m, v[s]);
        }
        m = fmaxf(m, __shfl_xor_sync(0xffffffffu, m, 1));
        float sum = 0.f;
        #pragma unroll
        for (int s = 0; s < 32; s++) { v[s] = __expf(v[s] - m); sum += v[s]; }
        sum += __shfl_xor_sync(0xffffffffu, sum, 1);
        float inv = 1.0f / sum;
        #pragma unroll
        for (int s = 0; s < 32; s++) {
            int j = p * 32 + s;
            float pv = v[s] * inv;
            __half ph = __float2half_rn(pv);
            sQh[row * SK2 + j] = ph;                                   // Ph
            sQl[row * SK2 + j] = __float2half_rn(pv - __half2float(ph)); // Pl
        }
    }
    __syncthreads();

    // ---- O = (Ph+Pl) V : B from transposed V tile ----
    {
        float acc[8][4];
        #pragma unroll
        for (int j = 0; j < 8; j++)
            #pragma unroll
            for (int r = 0; r < 4; r++) acc[j][r] = 0.f;
        #pragma unroll
        for (int ks = 0; ks < 4; ks++) {
            const int kc0 = ks * 16;
            uint32_t ph[4], pl[4], bf[8][2];
            uint32_t paddr = sb + (uint32_t)(TQH + (wm + a_lrow) * SK2 + kc0 + a_lcol) * 2;
            ldsm_x4(ph, paddr);
            ldsm_x4(pl, paddr + (uint32_t)(TQL - TQH) * 2);
            #pragma unroll
            for (int gg = 0; gg < 4; gg++) {
                uint32_t r[4];
                ldsm_x4(r, sb + (uint32_t)(TVT + (gg * 16 + b_lrow) * SK2 + kc0 + b_lcol) * 2);
                bf[2 * gg][0] = r[0]; bf[2 * gg][1] = r[1];
                bf[2 * gg + 1][0] = r[2]; bf[2 * gg + 1][1] = r[3];
            }
            #pragma unroll
            for (int j = 0; j < 8; j++) mma16816(acc[j], ph, bf[j]);
            #pragma unroll
            for (int j = 0; j < 8; j++) mma16816(acc[j], pl, bf[j]);
        }
        #pragma unroll
        for (int j = 0; j < 8; j++) {
            int col = h * HD + j * 8 + (lane & 3) * 2;
            int r0  = wm + (lane >> 2);
            *(float2*)(g_x + (size_t)(b * 64 + r0) * DIMC + col) =
                make_float2(acc[j][0], acc[j][1]);
            *(float2*)(g_x + (size_t)(b * 64 + r0 + 8) * DIMC + col) =
                make_float2(acc[j][2], acc[j][3]);
        }
    }
}

// ---------------------------------------------------------------------------
extern "C" void kernel_launch(void* const* d_in, const int* in_sizes, int n_in,
                              void* d_out, int out_size) {
    const float* q    = (const float*)d_in[0];
    const float* k    = (const float*)d_in[1];
    const float* v    = (const float*)d_in[2];
    const int*   mask = (const int*)  d_in[3];
    const float* Wq   = (const float*)d_in[4];
    const float* bq   = (const float*)d_in[5];
    const float* Wk   = (const float*)d_in[6];
    const float* bk   = (const float*)d_in[7];
    const float* Wv   = (const float*)d_in[8];
    const float* bv   = (const float*)d_in[9];
    const float* Wp   = (const float*)d_in[10];
    const float* bp   = (const float*)d_in[11];
    float* out = (float*)d_out;

    cudaFuncSetAttribute(gemm_mma, cudaFuncAttributeMaxDynamicSharedMemorySize, SMEM_G);
    cudaFuncSetAttribute(attn, cudaFuncAttributeMaxDynamicSharedMemorySize, SMEM_A);

    conv_w<<<4096, 256>>>(Wq, Wk, Wv, Wp);

    dim3 gg(DIMC / 256, MROWS / 128);
    gemm_mma<<<gg, 512, SMEM_G>>>(q, k, v, bq, nullptr, 0);
    gemm_mma<<<gg, 512, SMEM_G>>>(q, k, v, bk, nullptr, 1);
    gemm_mma<<<gg, 512, SMEM_G>>>(q, k, v, bv, nullptr, 2);

    attn<<<BATCH * HEADS, 128, SMEM_A>>>(mask);

    gemm_mma<<<gg, 512, SMEM_G>>>(q, k, v, bp, out, 3);
}